// round 13
// baseline (speedup 1.0000x reference)
#include <cuda_runtime.h>
#include <math.h>

#define NN 17
#define DD 512
#define HH 8
#define MM 256
#define CIN 515
#define NB 512          // grid; co-resident (4/SM * 148 = 592 >= 512)

typedef unsigned long long u64;

// ---------------- f32x2 helpers ----------------
__device__ __forceinline__ void ffma2(u64& acc, u64 a, u64 b) {
    asm("fma.rn.f32x2 %0, %1, %2, %0;" : "+l"(acc) : "l"(a), "l"(b));
}
__device__ __forceinline__ u64 dup2(float x) {
    u64 r; asm("mov.b64 %0, {%1, %1};" : "=l"(r) : "f"(x)); return r;
}
__device__ __forceinline__ float2 unpack2(u64 a) {
    float2 f; asm("mov.b64 {%0, %1}, %2;" : "=f"(f.x), "=f"(f.y) : "l"(a)); return f;
}

// ---------------- device scratch ----------------
__device__ float g_pA[16][HH][NN][DD];   // Xs@FC partials, 16 d-chunks (32 wide)
__device__ float g_f[HH][NN][DD];        // f = relu(Xs@FC)
__device__ float g_pB[32][HH][NN][MM];   // cat@W1 partials, 32 c-chunks (16 wide)
__device__ float g_patt[HH][8][NN * NN]; // partial logits per m-chunk [h][mc][n*17+k]
__device__ u64   g_attw[HH][NN * NN];    // dup pairs conv_w*softmax, [h][k*17+n]

// ---------------- device-wide barrier (replay-safe, monotonic release) ----------------
__device__ int g_cnt[4];
__device__ volatile unsigned g_rel[4];

__device__ __forceinline__ void gbar(int b) {
    __syncthreads();
    if (threadIdx.x == 0) {
        __threadfence();
        unsigned r0 = g_rel[b];
        if (atomicAdd(&g_cnt[b], 1) == NB - 1) {
            g_cnt[b] = 0;            // reset for next replay
            __threadfence();
            g_rel[b] = r0 + 1;       // monotonic release
        } else {
            while (g_rel[b] == r0) __nanosleep(64);
        }
        __threadfence();
    }
    __syncthreads();
}

// n-group helpers: 4 groups of nodes {0-4, 5-8, 9-12, 13-16}
__device__ __forceinline__ int grp_start(int g) { return (g == 0) ? 0 : (4 * g + 1); }
__device__ __forceinline__ int grp_of(int n)    { return (n < 5) ? 0 : ((n < 9) ? 1 : ((n < 13) ? 2 : 3)); }

// ================= The one persistent kernel =================
// smem union: A 6144 | B 3648 | C1 4736 | C2 1156 | C3 2112  -> 6144
#define SM_BYTES 6144
__global__ void __launch_bounds__(256, 4)
mega(const float* __restrict__ Xs, const float* __restrict__ ROIs,
     const float* __restrict__ FC, const float* __restrict__ W1,
     const float* __restrict__ b1, const float* __restrict__ W2,
     const float* __restrict__ b2, const float* __restrict__ conv_w,
     const float* __restrict__ conv_b, float* __restrict__ out, int out_size) {
    __shared__ __align__(16) char smbuf[SM_BYTES];
    const int bid = blockIdx.x, tid = threadIdx.x;

    // ======== Phase A: partial f = Xs @ FC ========
    // bid = dc(16, 32-wide) | ec(2bit, 64 e-pairs) | h(3bit)
    // threads: ng = tid>>6 (4 node-groups), e-pair P = ec*64 + (tid&63)
    {
        const int dc = bid & 15, ec = (bid >> 4) & 3, h = bid >> 6;
        const int d0 = dc * 32;
        const int g = tid >> 6;
        const int P = ec * 64 + (tid & 63);

        u64* xsd = reinterpret_cast<u64*>(smbuf);   // [(g*32+dd)*6 + j]
        for (int idx = tid; idx < 4 * 32 * 6; idx += 256) {
            int gg = idx / 192, r = idx % 192;
            int dd = r / 6, j = r % 6;
            int st = grp_start(gg);
            int cnt = (gg == 0) ? 5 : 4;
            float v = (j < cnt) ? Xs[(st + j) * DD + d0 + dd] : 0.f;
            xsd[idx] = dup2(v);
        }
        __syncthreads();

        u64 acc[5];
#pragma unroll
        for (int j = 0; j < 5; ++j) acc[j] = 0ull;

        const u64* fc = reinterpret_cast<const u64*>(FC)
                      + (size_t)h * 131072 + (size_t)d0 * 256 + P;
        u64 buf[6];
#pragma unroll
        for (int p = 0; p < 6; ++p) buf[p] = fc[(size_t)p * 256];

#pragma unroll
        for (int dd = 0; dd < 32; ++dd) {
            u64 w = buf[dd % 6];
            if (dd < 26) buf[dd % 6] = fc[(size_t)(dd + 6) * 256];
            const u64* row = &xsd[(g * 32 + dd) * 6];
            ulonglong2 q0 = *reinterpret_cast<const ulonglong2*>(row);
            ulonglong2 q1 = *reinterpret_cast<const ulonglong2*>(row + 2);
            u64 q4 = row[4];
            ffma2(acc[0], q0.x, w);
            ffma2(acc[1], q0.y, w);
            ffma2(acc[2], q1.x, w);
            ffma2(acc[3], q1.y, w);
            ffma2(acc[4], q4,   w);
        }
        const int st = grp_start(g);
        const int cnt = (g == 0) ? 5 : 4;
#pragma unroll
        for (int j = 0; j < 5; ++j)
            if (j < cnt)
                *reinterpret_cast<u64*>(&g_pA[dc][h][st + j][2 * P]) = acc[j];
    }
    gbar(0);

    // ======== Phase B: reduce f chunk + relu, partial cat @ W1 ========
    // bid = cc(32, 16-wide) | mg(1bit, 64 m-pairs) | h(3bit); cc==31 adds coords
    {
        const int cc = bid & 31, mg = (bid >> 5) & 1, h = bid >> 6;
        const int c0 = cc * 16;
        const int g = tid >> 6;
        const int mp = mg * 64 + (tid & 63);

        u64* catd = reinterpret_cast<u64*>(smbuf);   // [(g*19+row)*6 + j]
        for (int idx = tid; idx < 4 * 19 * 6; idx += 256) catd[idx] = 0ull;
        __syncthreads();

        for (int idx = tid; idx < NN * 16; idx += 256) {
            int n = idx >> 4, cp = idx & 15;
            float v = 0.f;
#pragma unroll
            for (int s = 0; s < 16; ++s) v += g_pA[s][h][n][c0 + cp];
            v = fmaxf(v, 0.f);
            if (mg == 0) g_f[h][n][c0 + cp] = v;   // write once (mg==1 duplicate skipped)
            int gg = grp_of(n);
            catd[(gg * 19 + cp) * 6 + (n - grp_start(gg))] = dup2(v);
        }
        if (cc == 31 && tid < NN * 3) {
            int n = tid / 3, jj = tid % 3;
            float v = ROIs[tid];
            int gg = grp_of(n);
            catd[(gg * 19 + 16 + jj) * 6 + (n - grp_start(gg))] = dup2(v);
        }
        __syncthreads();

        u64 acc[5];
#pragma unroll
        for (int j = 0; j < 5; ++j) acc[j] = 0ull;

        const u64* w1 = reinterpret_cast<const u64*>(W1)
                      + (size_t)h * 65920 + (size_t)c0 * 128 + mp;
        u64 buf[4];
#pragma unroll
        for (int p = 0; p < 4; ++p) buf[p] = w1[(size_t)p * 128];

#pragma unroll
        for (int i = 0; i < 16; ++i) {
            u64 w = buf[i & 3];
            if (i < 12) buf[i & 3] = w1[(size_t)(i + 4) * 128];
            const u64* row = &catd[(g * 19 + i) * 6];
            ulonglong2 q0 = *reinterpret_cast<const ulonglong2*>(row);
            ulonglong2 q1 = *reinterpret_cast<const ulonglong2*>(row + 2);
            u64 q4 = row[4];
            ffma2(acc[0], q0.x, w);
            ffma2(acc[1], q0.y, w);
            ffma2(acc[2], q1.x, w);
            ffma2(acc[3], q1.y, w);
            ffma2(acc[4], q4,   w);
        }
        if (cc == 31) {
#pragma unroll
            for (int jj = 0; jj < 3; ++jj) {
                u64 w = reinterpret_cast<const u64*>(W1)[(size_t)h * 65920 + (size_t)(DD + jj) * 128 + mp];
                const u64* row = &catd[(g * 19 + 16 + jj) * 6];
                ulonglong2 q0 = *reinterpret_cast<const ulonglong2*>(row);
                ulonglong2 q1 = *reinterpret_cast<const ulonglong2*>(row + 2);
                u64 q4 = row[4];
                ffma2(acc[0], q0.x, w);
                ffma2(acc[1], q0.y, w);
                ffma2(acc[2], q1.x, w);
                ffma2(acc[3], q1.y, w);
                ffma2(acc[4], q4,   w);
            }
        }
        const int st = grp_start(g);
        const int cnt = (g == 0) ? 5 : 4;
#pragma unroll
        for (int j = 0; j < 5; ++j)
            if (j < cnt)
                *reinterpret_cast<u64*>(&g_pB[cc][h][st + j][2 * mp]) = acc[j];
    }
    gbar(1);

    // ======== Phase C1: reduce g_pB + bias + tanh + partial logits ========
    // blocks 0..63: mc = bid&7, h = bid>>3; 32 m's each.
    if (bid < 64) {
        const int mc = bid & 7, h = bid >> 3;
        const int m0 = mc * 32;
        float* hdnf = reinterpret_cast<float*>(smbuf);            // [lm*20 + n]
        float* W2s  = reinterpret_cast<float*>(smbuf + 2560);     // [lm*17 + k]

        if (tid < NN * 8) {
            int n = tid >> 3, q = tid & 7;
            int m4 = m0 + q * 4;
            float4 s = *reinterpret_cast<const float4*>(b1 + h * MM + m4);
#pragma unroll
            for (int cc = 0; cc < 32; ++cc) {
                float4 v = *reinterpret_cast<const float4*>(&g_pB[cc][h][n][m4]);
                s.x += v.x; s.y += v.y; s.z += v.z; s.w += v.w;
            }
            int lm = q * 4;
            hdnf[(lm + 0) * 20 + n] = tanhf(s.x);
            hdnf[(lm + 1) * 20 + n] = tanhf(s.y);
            hdnf[(lm + 2) * 20 + n] = tanhf(s.z);
            hdnf[(lm + 3) * 20 + n] = tanhf(s.w);
        }
        if (tid < 136) {
            reinterpret_cast<float4*>(W2s)[tid] =
                reinterpret_cast<const float4*>(W2 + ((size_t)h * MM + m0) * NN)[tid];
        }
        __syncthreads();

        for (int idx = tid; idx < NN * NN; idx += 256) {
            int n = idx / NN, k = idx % NN;
            float s = 0.f;
#pragma unroll
            for (int lm = 0; lm < 32; ++lm)
                s = fmaf(hdnf[lm * 20 + n], W2s[lm * NN + k], s);
            g_patt[h][mc][idx] = s;
        }
    }
    gbar(2);

    // ======== Phase C2: reduce partials + bias, softmax, premult conv_w ========
    if (bid < 8) {
        const int h = bid;
        float* att = reinterpret_cast<float*>(smbuf);   // [k*17 + n]

        for (int idx = tid; idx < NN * NN; idx += 256) {
            int n = idx / NN, k = idx % NN;
            float s = b2[h * NN + k];
#pragma unroll
            for (int q = 0; q < 8; ++q) s += g_patt[h][q][idx];
            att[k * NN + n] = s;
        }
        __syncthreads();

        if (tid < NN) {
            const int k = tid;
            float mx = -1e30f;
#pragma unroll
            for (int n = 0; n < NN; ++n) mx = fmaxf(mx, att[k * NN + n]);
            float ex[NN], sum = 0.f;
#pragma unroll
            for (int n = 0; n < NN; ++n) { ex[n] = expf(att[k * NN + n] - mx); sum += ex[n]; }
            float scale = conv_w[h] / sum;
#pragma unroll
            for (int n = 0; n < NN; ++n) g_attw[h][k * NN + n] = dup2(ex[n] * scale);
        }
    }
    gbar(3);

    // ======== Phase C3: out = relu(sum_{h,n} attw*f + cb) + Xs ========
    if (bid < 2 * NN) {
        const int k = bid >> 1, ec = bid & 1;
        const int hg = tid >> 7, dt = tid & 127;
        const int P = ec * 128 + dt;

        u64*    aw   = reinterpret_cast<u64*>(smbuf);           // [h*17+n]
        float2* part = reinterpret_cast<float2*>(smbuf + 1088); // [128]

        if (tid < HH * NN)
            aw[tid] = g_attw[tid / NN][k * NN + tid % NN];
        __syncthreads();

        const u64* fb = reinterpret_cast<const u64*>(g_f) + P;
        const int hb = hg * 4;

        u64 acc[4];
#pragma unroll
        for (int j = 0; j < 4; ++j) acc[j] = 0ull;

#pragma unroll
        for (int hh = 0; hh < 4; ++hh) {
            const int h = hb + hh;
#pragma unroll
            for (int n = 0; n < NN; ++n) {
                u64 f2 = fb[(size_t)(h * NN + n) * 256];
                ffma2(acc[(hh * NN + n) & 3], aw[h * NN + n], f2);
            }
        }
        float2 a0 = unpack2(acc[0]), a1 = unpack2(acc[1]);
        float2 a2 = unpack2(acc[2]), a3 = unpack2(acc[3]);
        float2 s = make_float2(a0.x + a1.x + a2.x + a3.x,
                               a0.y + a1.y + a2.y + a3.y);
        if (hg == 1) part[dt] = s;
        __syncthreads();
        if (hg == 0) {
            const float cb = conv_b[0];
            float rx = s.x + part[dt].x + cb;
            float ry = s.y + part[dt].y + cb;
            const float2 xv = *reinterpret_cast<const float2*>(Xs + k * DD + 2 * P);
            float2 r = make_float2(fmaxf(rx, 0.f) + xv.x, fmaxf(ry, 0.f) + xv.y);
            *reinterpret_cast<float2*>(out + k * DD + 2 * P) = r;
        }
        if (k == 0 && ec == 0 && tid < NN * 3 && out_size >= NN * DD + NN * 3)
            out[NN * DD + tid] = ROIs[tid];
    }
}

// ---------------- launch ----------------
extern "C" void kernel_launch(void* const* d_in, const int* in_sizes, int n_in,
                              void* d_out, int out_size) {
    const float *Xs = 0, *ROIs = 0, *FC = 0, *W1 = 0, *b1 = 0, *W2 = 0, *b2 = 0,
                *cw = 0, *cb = 0;
    for (int i = 0; i < n_in; ++i) {
        const float* p = (const float*)d_in[i];
        switch (in_sizes[i]) {
            case NN * DD:       Xs = p; break;
            case NN * 3:        ROIs = p; break;
            case NN * NN:       /* adj */ break;
            case HH * DD * DD:  FC = p; break;
            case HH * CIN * MM: W1 = p; break;
            case HH * MM:       b1 = p; break;
            case HH * MM * NN:  W2 = p; break;
            case HH * NN:       b2 = p; break;
            case HH:            cw = p; break;
            case 1:             cb = p; break;
            default: break;
        }
    }
    float* out = (float*)d_out;

    mega<<<NB, 256>>>(Xs, ROIs, FC, W1, b1, W2, b2, cw, cb, out, out_size);
}

// round 14
// speedup vs baseline: 1.1893x; 1.1893x over previous
#include <cuda_runtime.h>
#include <math.h>

#define NN 17
#define DD 512
#define HH 8
#define MM 256
#define CIN 515
#define NB 256          // grid; co-resident (2/SM * 148 = 296 >= 256)

typedef unsigned long long u64;

// ---------------- f32x2 helpers ----------------
__device__ __forceinline__ void ffma2(u64& acc, u64 a, u64 b) {
    asm("fma.rn.f32x2 %0, %1, %2, %0;" : "+l"(acc) : "l"(a), "l"(b));
}
__device__ __forceinline__ u64 dup2(float x) {
    u64 r; asm("mov.b64 %0, {%1, %1};" : "=l"(r) : "f"(x)); return r;
}
__device__ __forceinline__ float2 unpack2(u64 a) {
    float2 f; asm("mov.b64 {%0, %1}, %2;" : "=f"(f.x), "=f"(f.y) : "l"(a)); return f;
}

// ---------------- device scratch ----------------
__device__ float g_pA[16][HH][NN][DD];   // Xs@FC partials, 16 d-chunks (32 wide)
__device__ float g_f[HH][NN][DD];        // f = relu(Xs@FC)
__device__ float g_pB[32][HH][NN][MM];   // cat@W1 partials, 32 c-chunks (16 wide)
__device__ float g_patt[HH][8][NN * NN]; // partial logits per m-chunk [h][mc][n*17+k]

// ---------------- device-wide barrier (replay-safe, monotonic release) ----------------
__device__ int g_cnt[3];
__device__ volatile unsigned g_rel[3];

__device__ __forceinline__ void gbar(int b) {
    __syncthreads();
    if (threadIdx.x == 0) {
        __threadfence();
        unsigned r0 = g_rel[b];
        if (atomicAdd(&g_cnt[b], 1) == NB - 1) {
            g_cnt[b] = 0;            // reset for next replay
            __threadfence();
            g_rel[b] = r0 + 1;       // monotonic release
        } else {
            while (g_rel[b] == r0) __nanosleep(64);
        }
        __threadfence();
    }
    __syncthreads();
}

// ================= The one persistent kernel =================
// smem union: A 5120 | B 3040 | C1 2560+2176 | C3 1088+1024+576
#define SM_BYTES 12800
__global__ void __launch_bounds__(256, 2)
mega(const float* __restrict__ Xs, const float* __restrict__ ROIs,
     const float* __restrict__ FC, const float* __restrict__ W1,
     const float* __restrict__ b1, const float* __restrict__ W2,
     const float* __restrict__ b2, const float* __restrict__ conv_w,
     const float* __restrict__ conv_b, float* __restrict__ out, int out_size) {
    __shared__ __align__(16) char smbuf[SM_BYTES];
    const int bid = blockIdx.x, tid = threadIdx.x;

    // ======== Phase A: partial f = Xs @ FC ========
    // bid = dc(16) | ec(1bit) | h(3bit); 32-wide d-chunks; group g over n.
    {
        const int dc = bid & 15, ec = (bid >> 4) & 1, h = bid >> 5;
        const int d0 = dc * 32;
        const int g = tid >> 7;
        const int P = ec * 128 + (tid & 127);   // e-pair

        u64* xsd = reinterpret_cast<u64*>(smbuf);   // [(g*32+dd)*10 + j]
        for (int idx = tid; idx < 32 * 20; idx += 256) {
            int dd = idx / 20, s = idx % 20;
            int gg = s / 10, j = s % 10;
            int n = gg ? 9 + j : j;
            bool ok = gg ? (j < 8) : (j < 9);
            float v = ok ? Xs[n * DD + d0 + dd] : 0.f;
            xsd[(gg * 32 + dd) * 10 + j] = dup2(v);
        }
        __syncthreads();

        u64 acc[10];
#pragma unroll
        for (int j = 0; j < 10; ++j) acc[j] = 0ull;

        const u64* fc = reinterpret_cast<const u64*>(FC)
                      + (size_t)h * 131072 + (size_t)d0 * 256 + P;
        u64 buf[8];
#pragma unroll
        for (int p = 0; p < 8; ++p) buf[p] = fc[(size_t)p * 256];

#pragma unroll
        for (int dd = 0; dd < 32; ++dd) {
            u64 w = buf[dd & 7];
            if (dd < 24) buf[dd & 7] = fc[(size_t)(dd + 8) * 256];
            const ulonglong2* row = reinterpret_cast<const ulonglong2*>(&xsd[(g * 32 + dd) * 10]);
#pragma unroll
            for (int j = 0; j < 5; ++j) {
                ulonglong2 q = row[j];
                ffma2(acc[2 * j],     q.x, w);
                ffma2(acc[2 * j + 1], q.y, w);
            }
        }
        if (g == 0) {
#pragma unroll
            for (int j = 0; j < 9; ++j)
                *reinterpret_cast<u64*>(&g_pA[dc][h][j][2 * P]) = acc[j];
        } else {
#pragma unroll
            for (int j = 0; j < 8; ++j)
                *reinterpret_cast<u64*>(&g_pA[dc][h][9 + j][2 * P]) = acc[j];
        }
    }
    gbar(0);

    // ======== Phase B: reduce f chunk + relu, partial cat @ W1 ========
    // bid = cc(32) | h(3bit); 16-wide c-chunks; cc==31 also coords.
    {
        const int cc = bid & 31, h = bid >> 5;
        const int c0 = cc * 16;
        const int g = tid >> 7;
        const int mp = tid & 127;   // m-pair

        u64* catd = reinterpret_cast<u64*>(smbuf);   // [(g*19+row)*10 + slot]
        for (int idx = tid; idx < 2 * 19 * 10; idx += 256) catd[idx] = 0ull;
        __syncthreads();

        for (int idx = tid; idx < NN * 16; idx += 256) {
            int n = idx >> 4, cp = idx & 15;
            float v = 0.f;
#pragma unroll
            for (int s = 0; s < 16; ++s) v += g_pA[s][h][n][c0 + cp];
            v = fmaxf(v, 0.f);
            g_f[h][n][c0 + cp] = v;
            if (n < 9) catd[(0 * 19 + cp) * 10 + n] = dup2(v);
            else       catd[(1 * 19 + cp) * 10 + (n - 9)] = dup2(v);
        }
        if (cc == 31 && tid < NN * 3) {
            int n = tid / 3, jj = tid % 3;
            float v = ROIs[tid];
            if (n < 9) catd[(0 * 19 + 16 + jj) * 10 + n] = dup2(v);
            else       catd[(1 * 19 + 16 + jj) * 10 + (n - 9)] = dup2(v);
        }
        __syncthreads();

        u64 acc[10];
#pragma unroll
        for (int j = 0; j < 10; ++j) acc[j] = 0ull;

        const u64* w1 = reinterpret_cast<const u64*>(W1)
                      + (size_t)h * 65920 + (size_t)c0 * 128 + mp;
        u64 buf[8];
#pragma unroll
        for (int p = 0; p < 8; ++p) buf[p] = w1[(size_t)p * 128];

#pragma unroll
        for (int i = 0; i < 16; ++i) {
            u64 w = buf[i & 7];
            if (i < 8) buf[i & 7] = w1[(size_t)(i + 8) * 128];
            const ulonglong2* row = reinterpret_cast<const ulonglong2*>(&catd[(g * 19 + i) * 10]);
#pragma unroll
            for (int j = 0; j < 5; ++j) {
                ulonglong2 q = row[j];
                ffma2(acc[2 * j],     q.x, w);
                ffma2(acc[2 * j + 1], q.y, w);
            }
        }
        if (cc == 31) {
#pragma unroll
            for (int jj = 0; jj < 3; ++jj) {
                u64 w = reinterpret_cast<const u64*>(W1)[(size_t)h * 65920 + (size_t)(DD + jj) * 128 + mp];
                const ulonglong2* row = reinterpret_cast<const ulonglong2*>(&catd[(g * 19 + 16 + jj) * 10]);
#pragma unroll
                for (int j = 0; j < 5; ++j) {
                    ulonglong2 q = row[j];
                    ffma2(acc[2 * j],     q.x, w);
                    ffma2(acc[2 * j + 1], q.y, w);
                }
            }
        }
        if (g == 0) {
#pragma unroll
            for (int j = 0; j < 9; ++j)
                *reinterpret_cast<u64*>(&g_pB[cc][h][j][2 * mp]) = acc[j];
        } else {
#pragma unroll
            for (int j = 0; j < 8; ++j)
                *reinterpret_cast<u64*>(&g_pB[cc][h][9 + j][2 * mp]) = acc[j];
        }
    }
    gbar(1);

    // ======== Phase C1: reduce g_pB + bias + tanh + partial logits ========
    // blocks 0..63: mc = bid&7, h = bid>>3; 32 m's each.
    if (bid < 64) {
        const int mc = bid & 7, h = bid >> 3;
        const int m0 = mc * 32;
        float* hdnf = reinterpret_cast<float*>(smbuf);            // [lm*20 + n]
        float* W2s  = reinterpret_cast<float*>(smbuf + 2560);     // [lm*17 + k]

        if (tid < NN * 8) {
            int n = tid >> 3, q = tid & 7;
            int m4 = m0 + q * 4;
            float4 s = *reinterpret_cast<const float4*>(b1 + h * MM + m4);
#pragma unroll
            for (int cc = 0; cc < 32; ++cc) {
                float4 v = *reinterpret_cast<const float4*>(&g_pB[cc][h][n][m4]);
                s.x += v.x; s.y += v.y; s.z += v.z; s.w += v.w;
            }
            int lm = q * 4;
            hdnf[(lm + 0) * 20 + n] = tanhf(s.x);
            hdnf[(lm + 1) * 20 + n] = tanhf(s.y);
            hdnf[(lm + 2) * 20 + n] = tanhf(s.z);
            hdnf[(lm + 3) * 20 + n] = tanhf(s.w);
        }
        // stage W2 slab [m0..m0+32) x 17, coalesced float4
        if (tid < 136) {
            reinterpret_cast<float4*>(W2s)[tid] =
                reinterpret_cast<const float4*>(W2 + ((size_t)h * MM + m0) * NN)[tid];
        }
        __syncthreads();

        // partial logits: patt[n][k] = sum_lm hdnf[lm][n] * W2s[lm][k]
        for (int idx = tid; idx < NN * NN; idx += 256) {
            int n = idx / NN, k = idx % NN;
            float s = 0.f;
#pragma unroll
            for (int lm = 0; lm < 32; ++lm)
                s = fmaf(hdnf[lm * 20 + n], W2s[lm * NN + k], s);
            g_patt[h][mc][idx] = s;
        }
    }
    gbar(2);

    // ======== Phase C3: per-k softmax + out = relu(sum_{h,n} attw*f + cb) + Xs ========
    // blocks 0..33: k = bid>>1, ec = bid&1; group hg over heads.
    // smem: aw u64[136] (1088) | part float2[128] (1024) | law f[8][18] (576)
    if (bid < 2 * NN) {
        const int k = bid >> 1, ec = bid & 1;
        const int hg = tid >> 7, dt = tid & 127;
        const int P = ec * 128 + dt;

        u64*    aw   = reinterpret_cast<u64*>(smbuf);                    // [h*17+n]
        float2* part = reinterpret_cast<float2*>(smbuf + 1088);          // [128]
        float*  law  = reinterpret_cast<float*>(smbuf + 1088 + 1024);    // [h*18+n]

        // 1) reduce logit partials for this k: law[h][n] = b2 + sum_q patt
        if (tid < HH * NN) {
            int h = tid / NN, n = tid % NN;
            float s = b2[h * NN + k];
#pragma unroll
            for (int q = 0; q < 8; ++q) s += g_patt[h][q][n * NN + k];
            law[h * 18 + n] = s;
        }
        __syncthreads();

        // 2) per-head softmax over n, premultiply conv_w -> aw dup pairs
        if (tid < HH) {
            const int h = tid;
            float mx = -1e30f;
#pragma unroll
            for (int n = 0; n < NN; ++n) mx = fmaxf(mx, law[h * 18 + n]);
            float ex[NN], sum = 0.f;
#pragma unroll
            for (int n = 0; n < NN; ++n) { ex[n] = expf(law[h * 18 + n] - mx); sum += ex[n]; }
            float scale = conv_w[h] / sum;
#pragma unroll
            for (int n = 0; n < NN; ++n) aw[h * NN + n] = dup2(ex[n] * scale);
        }
        __syncthreads();

        // 3) weighted sum over (h, n) of f + conv bias + relu + residual
        const u64* fb = reinterpret_cast<const u64*>(g_f) + P;
        const int hb = hg * 4;

        u64 acc[4];
#pragma unroll
        for (int j = 0; j < 4; ++j) acc[j] = 0ull;

#pragma unroll
        for (int hh = 0; hh < 4; ++hh) {
            const int h = hb + hh;
#pragma unroll
            for (int n = 0; n < NN; ++n) {
                u64 f2 = fb[(size_t)(h * NN + n) * 256];
                ffma2(acc[(hh * NN + n) & 3], aw[h * NN + n], f2);
            }
        }
        float2 a0 = unpack2(acc[0]), a1 = unpack2(acc[1]);
        float2 a2 = unpack2(acc[2]), a3 = unpack2(acc[3]);
        float2 s = make_float2(a0.x + a1.x + a2.x + a3.x,
                               a0.y + a1.y + a2.y + a3.y);
        if (hg == 1) part[dt] = s;
        __syncthreads();
        if (hg == 0) {
            const float cb = conv_b[0];
            float rx = s.x + part[dt].x + cb;
            float ry = s.y + part[dt].y + cb;
            const float2 xv = *reinterpret_cast<const float2*>(Xs + k * DD + 2 * P);
            float2 r = make_float2(fmaxf(rx, 0.f) + xv.x, fmaxf(ry, 0.f) + xv.y);
            *reinterpret_cast<float2*>(out + k * DD + 2 * P) = r;
        }
        if (k == 0 && ec == 0 && tid < NN * 3 && out_size >= NN * DD + NN * 3)
            out[NN * DD + tid] = ROIs[tid];
    }
}

// ---------------- launch ----------------
extern "C" void kernel_launch(void* const* d_in, const int* in_sizes, int n_in,
                              void* d_out, int out_size) {
    const float *Xs = 0, *ROIs = 0, *FC = 0, *W1 = 0, *b1 = 0, *W2 = 0, *b2 = 0,
                *cw = 0, *cb = 0;
    for (int i = 0; i < n_in; ++i) {
        const float* p = (const float*)d_in[i];
        switch (in_sizes[i]) {
            case NN * DD:       Xs = p; break;
            case NN * 3:        ROIs = p; break;
            case NN * NN:       /* adj */ break;
            case HH * DD * DD:  FC = p; break;
            case HH * CIN * MM: W1 = p; break;
            case HH * MM:       b1 = p; break;
            case HH * MM * NN:  W2 = p; break;
            case HH * NN:       b2 = p; break;
            case HH:            cw = p; break;
            case 1:             cb = p; break;
            default: break;
        }
    }
    float* out = (float*)d_out;

    mega<<<NB, 256>>>(Xs, ROIs, FC, W1, b1, W2, b2, cw, cb, out, out_size);
}